// round 17
// baseline (speedup 1.0000x reference)
#include <cuda_runtime.h>
#include <cuda_fp16.h>
#include <math.h>
#include <stdint.h>

#define NLVL   16
#define NPTS   (1 << 21)
#define TPB    256
#define MAXQ   3460000     // quads: levels 0..9 (683,431) + 10 (851,929) + 11 (1,915,456)

// fp16 quad scratch: per cell, 4 corner float2s as 8 halves = 16B.
__device__ __align__(16) uint4 g_quad[MAXQ];

struct LP {
    float rm1[NLVL];
    int   res[NLVL];
    int   offs[NLVL];      // entry offset of level l in params table
    int   dense[NLVL];     // 1 if level has a quad table (levels 0..11)
    int   hsrc[NLVL];      // 1 if quad table built from HASHED source (10,11)
    int   strm[NLVL];      // 1 if quad loads should be streaming (level 11)
    int   qoff[NLVL];      // quad-cell offset of level l in g_quad
    int   cbase[NLVL + 1]; // CELL prefix base, dense-source levels (builder)
};

static __device__ __forceinline__ uint4 pack_quad(float2 f00, float2 f10,
                                                  float2 f01, float2 f11)
{
    __half2 h00 = __floats2half2_rn(f00.x, f00.y);
    __half2 h10 = __floats2half2_rn(f10.x, f10.y);
    __half2 h01 = __floats2half2_rn(f01.x, f01.y);
    __half2 h11 = __floats2half2_rn(f11.x, f11.y);
    uint4 q;
    q.x = *reinterpret_cast<unsigned*>(&h00);
    q.y = *reinterpret_cast<unsigned*>(&h10);
    q.z = *reinterpret_cast<unsigned*>(&h01);
    q.w = *reinterpret_cast<unsigned*>(&h11);
    return q;
}

// ---------------- merged builder (R14 winner, unchanged) --------------------
__global__ void __launch_bounds__(TPB) build_all(
    const float2* __restrict__ tab, const LP lp,
    int ncells, int ndb, int ntx10, int ntx11)
{
    int bid = blockIdx.x;

    if (bid < ndb) {
        int i = bid * TPB + threadIdx.x;
        if (i >= ncells) return;

        int lvl = 0;
        #pragma unroll
        for (int l = 1; l < NLVL; l++)
            if (lp.dense[l] && !lp.hsrc[l] && i >= lp.cbase[l]) lvl = l;

        int j   = i - lp.cbase[lvl];
        int res = lp.res[lvl];
        int gy  = j / res;
        int gx  = j - gy * res;

        const float2* t = tab + lp.offs[lvl];
        int b = gy * res + gx;

        // Edge cells never queried (xy < 0.95); over-reads stay inside params.
        float2 f00 = __ldg(t + b);
        float2 f10 = __ldg(t + b + 1);
        float2 f01 = __ldg(t + b + res);
        float2 f11 = __ldg(t + b + res + 1);

        g_quad[lp.qoff[lvl] + j] = pack_quad(f00, f10, f01, f11);
        return;
    }

    int hb = bid - ndb;
    int lvl, bx, by;
    int n10 = ntx10 * ntx10;
    if (hb < n10) { lvl = 10; bx = hb % ntx10; by = hb / ntx10; }
    else          { hb -= n10; lvl = 11; bx = hb % ntx11; by = hb / ntx11; }

    int res = lp.res[lvl];
    int gx0 = bx << 5;
    int gy0 = by << 5;

    __shared__ float2 c[33][34];       // +1 pad column vs bank conflicts

    const float2* t  = tab + lp.offs[lvl];
    const float4* t4 = (const float4*)t;
    const unsigned M = (1u << 19) - 1u;

    for (int idx = threadIdx.x; idx < 33 * 17; idx += TPB) {
        int row  = idx / 17;
        int slot = idx - row * 17;
        unsigned h = (unsigned)(gy0 + row) * 2654435761u;
        if (slot < 16) {
            unsigned x  = (unsigned)(gx0 + (slot << 1));   // even
            unsigned i0 = (x ^ h) & M;
            float4 pr = __ldg(t4 + (i0 >> 1));
            float2 e0, e1;
            if (i0 & 1) { e0 = make_float2(pr.z, pr.w); e1 = make_float2(pr.x, pr.y); }
            else        { e0 = make_float2(pr.x, pr.y); e1 = make_float2(pr.z, pr.w); }
            c[row][(slot << 1)]     = e0;
            c[row][(slot << 1) + 1] = e1;
        } else {
            unsigned x = (unsigned)(gx0 + 32);
            c[row][32] = __ldg(t + ((x ^ h) & M));
        }
    }
    __syncthreads();

    int lx  = threadIdx.x & 31;
    int lyb = threadIdx.x >> 5;
    int qof = lp.qoff[lvl];

    #pragma unroll
    for (int k = 0; k < 4; k++) {
        int ly = lyb + (k << 3);
        int gx = gx0 + lx, gy = gy0 + ly;
        if (gx < res && gy < res) {
            uint4 q = pack_quad(c[ly][lx], c[ly][lx + 1],
                                c[ly + 1][lx], c[ly + 1][lx + 1]);
            g_quad[qof + gy * res + gx] = q;   // coalesced in lx
        }
    }
}

// ---------------- hashed kernel: levels 12..15 only (no g_quad dep) ---------
// Block 256 = 8 warps, 128 points. Warp w: point-group pg=w>>1 (16 points),
// lanes 0-15 -> level 12+2*(w&1), lanes 16-31 -> +1. Each thread: points
// {ptA, ptA+64}. Writes each point's last 32B (channels 12..15) via smem.
__global__ void __launch_bounds__(256) hashed_kernel(
    const float2* __restrict__ xy,
    const float2* __restrict__ tab,
    float2*       __restrict__ out,
    const LP lp)
{
    __shared__ float  s_rm1[4];
    __shared__ int    s_off[4];
    __shared__ float2 s_out[128 * 5];      // [pt][li], stride-5 pad

    if (threadIdx.x < 4) {
        s_rm1[threadIdx.x] = lp.rm1[12 + threadIdx.x];
        s_off[threadIdx.x] = lp.offs[12 + threadIdx.x];
    }
    __syncthreads();

    unsigned wid  = threadIdx.x >> 5;
    unsigned lane = threadIdx.x & 31u;
    unsigned pg   = wid >> 1;
    unsigned li   = ((wid & 1u) << 1) | (lane >> 4);    // level index 0..3
    unsigned ptA  = pg * 16u + (lane & 15u);            // block-local 0..63
    unsigned ptB  = ptA + 64u;
    unsigned base = blockIdx.x * 128u;

    float2 pA = __ldg(&xy[base + ptA]);
    float2 pB = __ldg(&xy[base + ptB]);

    float rm1 = s_rm1[li];
    const float2* t  = tab + s_off[li];
    const float4* t4 = (const float4*)t;
    const unsigned M = (1u << 19) - 1u;

    float2 o[2];
    float2 pts[2] = {pA, pB};
    #pragma unroll
    for (int s = 0; s < 2; s++) {
        float px = fmaf(pts[s].x, rm1, 0.5f);
        float py = fmaf(pts[s].y, rm1, 0.5f);
        float fx = floorf(px), fy = floorf(py);
        float wx = px - fx,    wy = py - fy;
        int gx = (int)fx, gy = (int)fy;

        unsigned h0 = (unsigned)gy       * 2654435761u;
        unsigned h1 = (unsigned)(gy + 1) * 2654435761u;
        int i00 = (int)(((unsigned)gx       ^ h0) & M);
        int i10 = (int)(((unsigned)(gx + 1) ^ h0) & M);
        int i01 = (int)(((unsigned)gx       ^ h1) & M);
        int i11 = (int)(((unsigned)(gx + 1) ^ h1) & M);

        float2 f00, f10, f01, f11;
        if ((gx & 1) == 0) {                 // aligned pairs {2k,2k+1}
            float4 r0 = __ldg(t4 + (i00 >> 1));
            float4 r1 = __ldg(t4 + (i01 >> 1));
            if (i00 & 1) { f00 = make_float2(r0.z, r0.w); f10 = make_float2(r0.x, r0.y); }
            else         { f00 = make_float2(r0.x, r0.y); f10 = make_float2(r0.z, r0.w); }
            if (i01 & 1) { f01 = make_float2(r1.z, r1.w); f11 = make_float2(r1.x, r1.y); }
            else         { f01 = make_float2(r1.x, r1.y); f11 = make_float2(r1.z, r1.w); }
        } else {
            f00 = __ldg(t + i00);
            f10 = __ldg(t + i10);
            f01 = __ldg(t + i01);
            f11 = __ldg(t + i11);
        }
        float ux = 1.0f - wx, uy = 1.0f - wy;
        float w00 = ux * uy, w10 = wx * uy, w01 = ux * wy, w11 = wx * wy;
        o[s] = make_float2(f00.x * w00 + f10.x * w10 + f01.x * w01 + f11.x * w11,
                           f00.y * w00 + f10.y * w10 + f01.y * w01 + f11.y * w11);
    }

    s_out[ptA * 5 + li] = o[0];
    s_out[ptB * 5 + li] = o[1];
    __syncthreads();

    // Flush: 128 points x 32B (channels 12..15) = 256 float4 chunks.
    unsigned c    = threadIdx.x;
    unsigned pt   = c >> 1;
    unsigned half = c & 1u;
    float2 a = s_out[pt * 5 + half * 2];
    float2 b = s_out[pt * 5 + half * 2 + 1];
    float4 v = make_float4(a.x, a.y, b.x, b.y);
    __stcs((float4*)(out + (size_t)(base + pt) * 16u + 12u + half * 2u), v);
}

// ---------------- quad kernel: levels 0..11 (all quad tables) ---------------
// Block 192 = 6 warps, 32 points. Warp w: lanes 0-15 -> level 2w, 16-31 ->
// 2w+1. Each thread: points {pt, pt+16}. Writes channels 0..11 (96B/point).
__global__ void __launch_bounds__(192) quad_kernel(
    const float2* __restrict__ xy,
    float2*       __restrict__ out,
    const LP lp)
{
    __shared__ float  s_rm1[12];
    __shared__ int    s_res[12], s_qoff[12], s_strm[12];
    __shared__ float2 s_out[32 * 13];      // [pt][lvl], stride-13 pad

    if (threadIdx.x < 12) {
        int t = threadIdx.x;
        s_rm1[t]  = lp.rm1[t];
        s_res[t]  = lp.res[t];
        s_qoff[t] = lp.qoff[t];
        s_strm[t] = lp.strm[t];
    }
    __syncthreads();

    unsigned wid  = threadIdx.x >> 5;
    unsigned lane = threadIdx.x & 31u;
    unsigned pt0  = lane & 15u;
    unsigned pt1  = pt0 + 16u;
    unsigned lvl  = (wid << 1) | (lane >> 4);       // 0..11

    unsigned base = blockIdx.x * 32u;

    float2 pA = __ldg(&xy[base + pt0]);
    float2 pB = __ldg(&xy[base + pt1]);

    float rm1 = s_rm1[lvl];
    int   res = s_res[lvl];

    float pxA = fmaf(pA.x, rm1, 0.5f), pyA = fmaf(pA.y, rm1, 0.5f);
    float pxB = fmaf(pB.x, rm1, 0.5f), pyB = fmaf(pB.y, rm1, 0.5f);
    float fxA = floorf(pxA), fyA = floorf(pyA);
    float fxB = floorf(pxB), fyB = floorf(pyB);
    float wxA = pxA - fxA,  wyA = pyA - fyA;
    float wxB = pxB - fxB,  wyB = pyB - fyB;
    int gxA = (int)fxA, gyA = (int)fyA;
    int gxB = (int)fxB, gyB = (int)fyB;

    const uint4* qb = &g_quad[s_qoff[lvl]];
    const uint4* pa = qb + gxA + gyA * res;
    const uint4* pb = qb + gxB + gyB * res;
    uint4 qA, qB;
    if (s_strm[lvl]) {                     // level 11: ~1x reuse, evict-first
        qA = __ldcs(pa);
        qB = __ldcs(pb);
    } else {
        qA = __ldg(pa);
        qB = __ldg(pb);
    }

    {
        float2 f00 = __half22float2(*reinterpret_cast<__half2*>(&qA.x));
        float2 f10 = __half22float2(*reinterpret_cast<__half2*>(&qA.y));
        float2 f01 = __half22float2(*reinterpret_cast<__half2*>(&qA.z));
        float2 f11 = __half22float2(*reinterpret_cast<__half2*>(&qA.w));
        float ux = 1.0f - wxA, uy = 1.0f - wyA;
        float w00 = ux * uy, w10 = wxA * uy, w01 = ux * wyA, w11 = wxA * wyA;
        s_out[pt0 * 13 + lvl] =
            make_float2(f00.x * w00 + f10.x * w10 + f01.x * w01 + f11.x * w11,
                        f00.y * w00 + f10.y * w10 + f01.y * w01 + f11.y * w11);
    }
    {
        float2 f00 = __half22float2(*reinterpret_cast<__half2*>(&qB.x));
        float2 f10 = __half22float2(*reinterpret_cast<__half2*>(&qB.y));
        float2 f01 = __half22float2(*reinterpret_cast<__half2*>(&qB.z));
        float2 f11 = __half22float2(*reinterpret_cast<__half2*>(&qB.w));
        float ux = 1.0f - wxB, uy = 1.0f - wyB;
        float w00 = ux * uy, w10 = wxB * uy, w01 = ux * wyB, w11 = wxB * wyB;
        s_out[pt1 * 13 + lvl] =
            make_float2(f00.x * w00 + f10.x * w10 + f01.x * w01 + f11.x * w11,
                        f00.y * w00 + f10.y * w10 + f01.y * w01 + f11.y * w11);
    }
    __syncthreads();

    // Flush: 32 points x 96B (channels 0..11) = 192 float4 chunks, 1/thread.
    unsigned p  = threadIdx.x;
    unsigned pt = p / 6u;
    unsigned cp = p - pt * 6u;
    float2 a = s_out[pt * 13 + cp * 2];
    float2 b = s_out[pt * 13 + cp * 2 + 1];
    float4 v = make_float4(a.x, a.y, b.x, b.y);
    __stcs((float4*)(out + (size_t)(base + pt) * 16u + cp * 2u), v);
}

extern "C" void kernel_launch(void* const* d_in, const int* in_sizes, int n_in,
                              void* d_out, int out_size)
{
    (void)in_sizes; (void)n_in; (void)out_size;

    // One-time stream/event setup for the builder||hashed fork in the graph.
    static int          s_init = 0;
    static cudaStream_t s_side;
    static cudaEvent_t  s_e0, s_e1;
    if (!s_init) {
        cudaStreamCreateWithFlags(&s_side, cudaStreamNonBlocking);
        cudaEventCreateWithFlags(&s_e0, cudaEventDisableTiming);
        cudaEventCreateWithFlags(&s_e1, cudaEventDisableTiming);
        s_init = 1;
    }

    // Mirror the reference's level-geometry computation exactly (same libm).
    LP lp;
    long long sizes[NLVL];
    int       resv [NLVL];
    double log2s = log2(1.5);
    long long off = 0;
    for (int l = 0; l < NLVL; l++) {
        double scale = pow(2.0, (double)l * log2s) * 16.0 - 1.0;
        int r = (int)ceil(scale) + 1;
        long long sz = (((long long)r * (long long)r + 7) / 8) * 8;
        if (sz > (1LL << 19)) sz = (1LL << 19);
        resv[l]    = r;
        sizes[l]   = sz;
        lp.rm1[l]  = (float)(r - 1);
        lp.res[l]  = r;
        lp.offs[l] = (int)off;
        off += sz;
    }
    long long qoff = 0;
    int ncells = 0;                        // dense-source cells (1 thread each)
    for (int l = 0; l < NLVL; l++) {
        int trueDense = (sizes[l] >= (long long)resv[l] * resv[l]) ? 1 : 0;
        int quad = trueDense || (l <= 11);
        lp.dense[l] = quad;
        lp.hsrc[l]  = quad && !trueDense;   // levels 10, 11
        lp.strm[l]  = (l == 11) ? 1 : 0;    // ~1x reuse -> streaming loads
        lp.qoff[l]  = 0;
        lp.cbase[l] = ncells;
        if (quad) {
            lp.qoff[l] = (int)qoff;
            qoff += (long long)resv[l] * resv[l];
            if (trueDense) ncells += resv[l] * resv[l];
        }
    }
    lp.cbase[NLVL] = ncells;

    const float2* xy  = (const float2*)d_in[0];
    const float2* tab = (const float2*)d_in[1];
    float2*       out = (float2*)d_out;

    int ndb   = (ncells + TPB - 1) / TPB;            // dense builder blocks
    int ntx10 = (resv[10] + 31) >> 5;
    int ntx11 = (resv[11] + 31) >> 5;
    int nblocks = ndb + ntx10 * ntx10 + ntx11 * ntx11;

    // Fork: builder runs on side stream CONCURRENTLY with the hashed kernel
    // (which does not touch g_quad); join before the quad kernel.
    cudaEventRecord(s_e0, 0);
    cudaStreamWaitEvent(s_side, s_e0, 0);
    build_all<<<nblocks, TPB, 0, s_side>>>(tab, lp, ncells, ndb, ntx10, ntx11);
    hashed_kernel<<<NPTS / 128, 256>>>(xy, tab, out, lp);
    cudaEventRecord(s_e1, s_side);
    cudaStreamWaitEvent(0, s_e1, 0);
    quad_kernel<<<NPTS / 32, 192>>>(xy, out, lp);
}